// round 5
// baseline (speedup 1.0000x reference)
#include <cuda_runtime.h>
#include <math.h>

#define BDIM 32
#define TDIM 32
#define IDIM 256
#define HDIM 512
#define HS 64
#define MS 2048
#define NHEADS 4
#define ODIM 256
#define NKEYS 8          // 4 read + 4 write
#define LCHUNKS 8        // logits chunks per batch (256 rows each)
#define NB 128           // persistent blocks (<=148 SMs -> all co-resident)

// ---------------- persistent state ----------------
__device__ float g_h[2][BDIM * HDIM];
__device__ float g_c[BDIM * HDIM];
__device__ float g_read[BDIM * NHEADS * HS];
__device__ float g_rk[BDIM * NHEADS * HS];
__device__ float g_wk[BDIM * NHEADS * HS];
__device__ float g_ws[BDIM * NHEADS];
__device__ float g_logits[BDIM * NKEYS * MS];
__device__ float g_pmax[BDIM * NKEYS * LCHUNKS];
__device__ float g_psum[BDIM * NKEYS * LCHUNKS];
__device__ float g_rpart[BDIM * 32 * NHEADS * HS];

// barrier state (ends balanced every launch; gen continues across replays)
__device__ unsigned g_arrive[NB];
__device__ unsigned g_release;

__device__ __forceinline__ float sigmoidf_(float x) { return 1.f / (1.f + expf(-x)); }

// ---- grid barrier: flag-array arrive, block-0 parallel poll, release flag ----
__device__ __forceinline__ void grid_sync(unsigned gen) {
    __threadfence();            // publish this block's phase writes
    __syncthreads();
    if (threadIdx.x == 0)
        *(volatile unsigned*)&g_arrive[blockIdx.x] = gen;
    if (blockIdx.x == 0) {
        if (threadIdx.x < NB)
            while (*(volatile unsigned*)&g_arrive[threadIdx.x] != gen) __nanosleep(20);
        __syncthreads();
        if (threadIdx.x == 0)
            *(volatile unsigned*)&g_release = gen;
    } else {
        if (threadIdx.x == 0)
            while (*(volatile unsigned*)&g_release != gen) __nanosleep(20);
    }
    __syncthreads();
    __threadfence();            // acquire: gpu-scope fence flushes L1D (CCTL.IVALL)
}

// ---------------- phase bodies (virtual-block versions of the R2 kernels) ----------------

__device__ __forceinline__ void lstm_body(
    float* sh, const float* __restrict__ x, const float* __restrict__ W_ih,
    const float* __restrict__ W_hh, const float* __restrict__ b_ih,
    const float* __restrict__ b_hh, int p, int t, int vb)
{
    float (*inp_s)[1024] = (float(*)[1024])sh;   // 32KB
    const float* __restrict__ h_prev = g_h[p];
    float* __restrict__ h_new = g_h[p ^ 1];
    int tid = threadIdx.x;
    int bb0 = (vb >> 6) * 8;         // batch group 0..3
    int jg = vb & 63;                // j group 0..63
    for (int idx = tid; idx < 8 * 1024; idx += 256) {
        int bb = idx >> 10, k = idx & 1023;
        int b = bb0 + bb;
        float v;
        if (k < 256)      v = x[(b * TDIM + t) * IDIM + k];
        else if (k < 512) v = g_read[b * 256 + (k - 256)];
        else              v = h_prev[b * HDIM + (k - 512)];
        inp_s[bb][k] = v;
    }
    __syncthreads();
    int w = tid >> 5, lane = tid & 31;
    int j = jg * 8 + w;
    float acc[4][8];
#pragma unroll
    for (int g = 0; g < 4; g++)
#pragma unroll
        for (int bb = 0; bb < 8; bb++) acc[g][bb] = 0.f;

#pragma unroll
    for (int c = 0; c < 8; c++) {
        const float* Wsrc = (c < 4) ? W_ih : W_hh;
        int kw = ((c & 3) * 128) + lane * 4;
        float4 w4[4];
#pragma unroll
        for (int g = 0; g < 4; g++)
            w4[g] = *(const float4*)&Wsrc[(size_t)(g * HDIM + j) * HDIM + kw];
        int ks = c * 128 + lane * 4;
#pragma unroll
        for (int bb = 0; bb < 8; bb++) {
            float4 a4 = *(const float4*)&inp_s[bb][ks];
#pragma unroll
            for (int g = 0; g < 4; g++) {
                acc[g][bb] = fmaf(w4[g].x, a4.x, acc[g][bb]);
                acc[g][bb] = fmaf(w4[g].y, a4.y, acc[g][bb]);
                acc[g][bb] = fmaf(w4[g].z, a4.z, acc[g][bb]);
                acc[g][bb] = fmaf(w4[g].w, a4.w, acc[g][bb]);
            }
        }
    }
    float res = 0.f;
#pragma unroll
    for (int g = 0; g < 4; g++)
#pragma unroll
        for (int bb = 0; bb < 8; bb++) {
            float v = acc[g][bb];
            v += __shfl_xor_sync(0xffffffffu, v, 16);
            v += __shfl_xor_sync(0xffffffffu, v, 8);
            v += __shfl_xor_sync(0xffffffffu, v, 4);
            v += __shfl_xor_sync(0xffffffffu, v, 2);
            v += __shfl_xor_sync(0xffffffffu, v, 1);
            if (lane == g * 8 + bb) res = v;
        }
    int bb = lane & 7;
    float iv = __shfl_sync(0xffffffffu, res, bb);
    float fv = __shfl_sync(0xffffffffu, res, 8 + bb);
    float gv = __shfl_sync(0xffffffffu, res, 16 + bb);
    float ov = __shfl_sync(0xffffffffu, res, 24 + bb);
    if (lane < 8) {
        int b = bb0 + lane;
        iv += b_ih[j] + b_hh[j];
        fv += b_ih[HDIM + j] + b_hh[HDIM + j];
        gv += b_ih[2 * HDIM + j] + b_hh[2 * HDIM + j];
        ov += b_ih[3 * HDIM + j] + b_hh[3 * HDIM + j];
        float cold = g_c[b * HDIM + j];
        float cn = sigmoidf_(fv) * cold + sigmoidf_(iv) * tanhf(gv);
        float hn = sigmoidf_(ov) * tanhf(cn);
        g_c[b * HDIM + j] = cn;
        h_new[b * HDIM + j] = hn;
    }
}

__device__ __forceinline__ void head_body(
    float* sh, const float* __restrict__ W_head, const float* __restrict__ b_head,
    int pn, int vb)
{
    float (*h_s)[512] = (float(*)[512])sh;       // 16KB
    const float* __restrict__ h_new = g_h[pn];
    int tid = threadIdx.x;
    int bg = vb / 65, rg = vb % 65;
    int bb0 = bg * 8;
    for (int idx = tid; idx < 8 * 512; idx += 256) {
        int bb = idx >> 9, k = idx & 511;
        h_s[bb][k] = h_new[(bb0 + bb) * HDIM + k];
    }
    __syncthreads();
    int w = tid >> 5, lane = tid & 31;
    int r = rg * 8 + w;
    if (r < NHEADS * 129) {
        int n = r / 129, jj = r % 129;
        int wrow = n * 2115 + jj;
        float acc[8];
#pragma unroll
        for (int bb = 0; bb < 8; bb++) acc[bb] = 0.f;
#pragma unroll
        for (int c = 0; c < 4; c++) {
            int kw = c * 128 + lane * 4;
            float4 w4 = *(const float4*)&W_head[(size_t)wrow * HDIM + kw];
#pragma unroll
            for (int bb = 0; bb < 8; bb++) {
                float4 a4 = *(const float4*)&h_s[bb][kw];
                acc[bb] = fmaf(w4.x, a4.x, acc[bb]);
                acc[bb] = fmaf(w4.y, a4.y, acc[bb]);
                acc[bb] = fmaf(w4.z, a4.z, acc[bb]);
                acc[bb] = fmaf(w4.w, a4.w, acc[bb]);
            }
        }
        float res = 0.f;
#pragma unroll
        for (int bb = 0; bb < 8; bb++) {
            float v = acc[bb];
            v += __shfl_xor_sync(0xffffffffu, v, 16);
            v += __shfl_xor_sync(0xffffffffu, v, 8);
            v += __shfl_xor_sync(0xffffffffu, v, 4);
            v += __shfl_xor_sync(0xffffffffu, v, 2);
            v += __shfl_xor_sync(0xffffffffu, v, 1);
            if (lane == bb) res = v;
        }
        if (lane < 8) {
            int b = bb0 + lane;
            float val = res + b_head[wrow];
            if (jj < HS)          g_rk[(b * NHEADS + n) * HS + jj] = val;
            else if (jj < 2 * HS) g_wk[(b * NHEADS + n) * HS + (jj - HS)] = val;
            else                  g_ws[b * NHEADS + n] = sigmoidf_(val);
        }
    }
}

__device__ __forceinline__ void logits_body(
    float* sh, const float* __restrict__ mem, int vb)
{
    float (*key_s)[64] = (float(*)[64])sh;           // 512 floats
    float (*wred)[8]   = (float(*)[8])(sh + 512);    // 64
    float* bmax        = sh + 576;                   // 8
    int tid = threadIdx.x;
    int chunk = vb & 7, b = vb >> 3;
    for (int idx = tid; idx < NKEYS * 64; idx += 256) {
        int key = idx >> 6, h = idx & 63, n = key & 3;
        key_s[key][h] = (key < 4) ? g_rk[(b * NHEADS + n) * HS + h]
                                  : g_wk[(b * NHEADS + n) * HS + h];
    }
    __syncthreads();

    int m = chunk * 256 + tid;
    const float* mrow = &mem[((size_t)b * MS + m) * HS];
    float acc[NKEYS];
#pragma unroll
    for (int k = 0; k < NKEYS; k++) acc[k] = 0.f;
#pragma unroll
    for (int hq = 0; hq < 16; hq++) {
        float4 v = *(const float4*)&mrow[hq * 4];
#pragma unroll
        for (int k = 0; k < NKEYS; k++) {
            float4 kv = *(const float4*)&key_s[k][hq * 4];
            acc[k] = fmaf(v.x, kv.x, acc[k]);
            acc[k] = fmaf(v.y, kv.y, acc[k]);
            acc[k] = fmaf(v.z, kv.z, acc[k]);
            acc[k] = fmaf(v.w, kv.w, acc[k]);
        }
    }
    const float scale = 0.125f;
#pragma unroll
    for (int k = 0; k < NKEYS; k++) {
        acc[k] *= scale;
        g_logits[((size_t)b * NKEYS + k) * MS + m] = acc[k];
    }

    int w = tid >> 5, lane = tid & 31;
#pragma unroll
    for (int k = 0; k < NKEYS; k++) {
        float v = acc[k];
        v = fmaxf(v, __shfl_xor_sync(0xffffffffu, v, 16));
        v = fmaxf(v, __shfl_xor_sync(0xffffffffu, v, 8));
        v = fmaxf(v, __shfl_xor_sync(0xffffffffu, v, 4));
        v = fmaxf(v, __shfl_xor_sync(0xffffffffu, v, 2));
        v = fmaxf(v, __shfl_xor_sync(0xffffffffu, v, 1));
        if (lane == 0) wred[k][w] = v;
    }
    __syncthreads();
    if (tid < NKEYS) {
        float v = wred[tid][0];
#pragma unroll
        for (int i = 1; i < 8; i++) v = fmaxf(v, wred[tid][i]);
        bmax[tid] = v;
    }
    __syncthreads();
#pragma unroll
    for (int k = 0; k < NKEYS; k++) {
        float v = expf(acc[k] - bmax[k]);
        v += __shfl_xor_sync(0xffffffffu, v, 16);
        v += __shfl_xor_sync(0xffffffffu, v, 8);
        v += __shfl_xor_sync(0xffffffffu, v, 4);
        v += __shfl_xor_sync(0xffffffffu, v, 2);
        v += __shfl_xor_sync(0xffffffffu, v, 1);
        if (lane == 0) wred[k][w] = v;
    }
    __syncthreads();
    if (tid < NKEYS) {
        float s = 0.f;
#pragma unroll
        for (int i = 0; i < 8; i++) s += wred[tid][i];
        g_pmax[(b * NKEYS + tid) * LCHUNKS + chunk] = bmax[tid];
        g_psum[(b * NKEYS + tid) * LCHUNKS + chunk] = s;
    }
}

__device__ __forceinline__ void attend_body(float* sh, float* __restrict__ mem, int vb)
{
    float* gm          = sh;                          // 8
    float* ginv        = sh + 8;                      // 8
    float (*w_s)[64]   = (float(*)[64])(sh + 16);     // 512
    float (*swk_s)[64] = (float(*)[64])(sh + 528);    // 256
    float (*sred)[256] = (float(*)[256])(sh + 784);   // 1024
    int tid = threadIdx.x;
    int chunk = vb & 31, b = vb >> 5;

    if (tid < NKEYS) {
        int key = tid;
        const float* pm = &g_pmax[(b * NKEYS + key) * LCHUNKS];
        const float* ps = &g_psum[(b * NKEYS + key) * LCHUNKS];
        float m0 = pm[0];
#pragma unroll
        for (int i = 1; i < LCHUNKS; i++) m0 = fmaxf(m0, pm[i]);
        float s = 0.f;
#pragma unroll
        for (int i = 0; i < LCHUNKS; i++) s += expf(pm[i] - m0) * ps[i];
        gm[key] = m0;
        ginv[key] = 1.f / s;
    }
    {
        int n = tid >> 6, h = tid & 63;
        swk_s[n][h] = g_ws[b * NHEADS + n] * g_wk[(b * NHEADS + n) * HS + h];
    }
    __syncthreads();
    for (int idx = tid; idx < NKEYS * 64; idx += 256) {
        int key = idx >> 6, row = idx & 63;
        float lg = g_logits[((size_t)b * NKEYS + key) * MS + chunk * 64 + row];
        w_s[key][row] = expf(lg - gm[key]) * ginv[key];
    }
    __syncthreads();

    int h = tid & 63, ms = tid >> 6;
    float v[16];
    float acc[NHEADS] = {0.f, 0.f, 0.f, 0.f};
#pragma unroll
    for (int mi = 0; mi < 16; mi++) {
        int row = mi * 4 + ms;
        v[mi] = mem[((size_t)b * MS + chunk * 64 + row) * HS + h];
#pragma unroll
        for (int n = 0; n < NHEADS; n++)
            acc[n] = fmaf(w_s[n][row], v[mi], acc[n]);
    }
#pragma unroll
    for (int mi = 0; mi < 16; mi++) {
        int row = mi * 4 + ms;
        float val = v[mi];
#pragma unroll
        for (int n = 0; n < NHEADS; n++)
            val = fmaf(w_s[4 + n][row], swk_s[n][h], val);
        mem[((size_t)b * MS + chunk * 64 + row) * HS + h] = val;
    }
#pragma unroll
    for (int n = 0; n < NHEADS; n++) sred[ms][n * 64 + h] = acc[n];
    __syncthreads();
    {
        float tot = sred[0][tid] + sred[1][tid] + sred[2][tid] + sred[3][tid];
        g_rpart[((size_t)b * 32 + chunk) * 256 + tid] = tot;
    }
}

__device__ __forceinline__ void rr_body(int vb)
{
    int tid = threadIdx.x, b = vb;
    float s = 0.f;
#pragma unroll
    for (int ch = 0; ch < 32; ch++) s += g_rpart[((size_t)b * 32 + ch) * 256 + tid];
    g_read[b * 256 + tid] = s;
}

__device__ __forceinline__ void out_body(
    float* sh, const float* __restrict__ W_out, const float* __restrict__ b_out,
    float* __restrict__ out, int pn, int t, int vb)
{
    float (*cat_s)[768] = (float(*)[768])sh;     // 24KB
    const float* __restrict__ h_new = g_h[pn];
    int tid = threadIdx.x;
    int og = vb & 31, bg = vb >> 5;
    int bb0 = bg * 8;
    for (int idx = tid; idx < 8 * 768; idx += 256) {
        int bb = idx / 768, k = idx % 768;
        cat_s[bb][k] = (k < 512) ? h_new[(bb0 + bb) * HDIM + k]
                                 : g_read[(bb0 + bb) * 256 + (k - 512)];
    }
    __syncthreads();
    int w = tid >> 5, lane = tid & 31;
    int o = og * 8 + w;
    float acc[8];
#pragma unroll
    for (int bb = 0; bb < 8; bb++) acc[bb] = 0.f;
#pragma unroll
    for (int c = 0; c < 6; c++) {
        int kw = c * 128 + lane * 4;
        float4 w4 = *(const float4*)&W_out[(size_t)o * 768 + kw];
#pragma unroll
        for (int bb = 0; bb < 8; bb++) {
            float4 a4 = *(const float4*)&cat_s[bb][kw];
            acc[bb] = fmaf(w4.x, a4.x, acc[bb]);
            acc[bb] = fmaf(w4.y, a4.y, acc[bb]);
            acc[bb] = fmaf(w4.z, a4.z, acc[bb]);
            acc[bb] = fmaf(w4.w, a4.w, acc[bb]);
        }
    }
    float res = 0.f;
#pragma unroll
    for (int bb = 0; bb < 8; bb++) {
        float v = acc[bb];
        v += __shfl_xor_sync(0xffffffffu, v, 16);
        v += __shfl_xor_sync(0xffffffffu, v, 8);
        v += __shfl_xor_sync(0xffffffffu, v, 4);
        v += __shfl_xor_sync(0xffffffffu, v, 2);
        v += __shfl_xor_sync(0xffffffffu, v, 1);
        if (lane == bb) res = v;
    }
    if (lane < 8) {
        int b = bb0 + lane;
        out[((size_t)b * TDIM + t) * ODIM + o] = res + b_out[o];
    }
}

// ---------------- the persistent kernel ----------------
__global__ void __launch_bounds__(256) k_persist(
    const float* __restrict__ x, const float* __restrict__ W_ih,
    const float* __restrict__ W_hh, const float* __restrict__ b_ih,
    const float* __restrict__ b_hh, const float* __restrict__ W_head,
    const float* __restrict__ b_head, const float* __restrict__ W_out,
    const float* __restrict__ b_out,
    float* __restrict__ out, float* __restrict__ mem,
    float* __restrict__ out_h, float* __restrict__ out_c)
{
    __shared__ float sh[8192];   // 32KB scratch shared by all phases
    int tid = threadIdx.x;
    unsigned gen = *(volatile unsigned*)&g_release;   // barrier generation base

    // ---- phase: init ----
    for (int idx = blockIdx.x * 256 + tid; idx < BDIM * MS * HS; idx += NB * 256)
        mem[idx] = 0.f;
    for (int idx = blockIdx.x * 256 + tid; idx < BDIM * HDIM; idx += NB * 256) {
        g_h[0][idx] = 0.f; g_c[idx] = 0.f;
    }
    for (int idx = blockIdx.x * 256 + tid; idx < BDIM * NHEADS * HS; idx += NB * 256)
        g_read[idx] = 0.f;
    grid_sync(++gen);

    for (int t = 0; t < TDIM; t++) {
        int p = t & 1;       // h_prev buffer; also the buffer holding h[t-1]
        int pn = p ^ 1;      // h_new buffer

        // ---- phase: lstm(t) [+ out(t-1)] ----
        int nv = (t > 0) ? 384 : 256;
        for (int vb = blockIdx.x; vb < nv; vb += NB) {
            if (vb < 256) lstm_body(sh, x, W_ih, W_hh, b_ih, b_hh, p, t, vb);
            else          out_body(sh, W_out, b_out, out, p, t - 1, vb - 256);
            __syncthreads();
        }
        grid_sync(++gen);

        // ---- phase: head ----
        for (int vb = blockIdx.x; vb < 260; vb += NB) {
            head_body(sh, W_head, b_head, pn, vb);
            __syncthreads();
        }
        grid_sync(++gen);

        // ---- phase: logits ----
        for (int vb = blockIdx.x; vb < 256; vb += NB) {
            logits_body(sh, mem, vb);
            __syncthreads();
        }
        grid_sync(++gen);

        // ---- phase: attend ----
        for (int vb = blockIdx.x; vb < 1024; vb += NB) {
            attend_body(sh, mem, vb);
            __syncthreads();
        }
        grid_sync(++gen);

        // ---- phase: read reduce ----
        if (blockIdx.x < 32) rr_body(blockIdx.x);
        grid_sync(++gen);
    }

    // ---- phase: out(31) + final state copy ----
    for (int vb = blockIdx.x; vb < 128; vb += NB) {
        out_body(sh, W_out, b_out, out, 0, TDIM - 1, vb);
        __syncthreads();
    }
    for (int idx = blockIdx.x * 256 + tid; idx < BDIM * HDIM; idx += NB * 256) {
        out_h[idx] = g_h[0][idx];    // after 32 steps h lives in buffer 0
        out_c[idx] = g_c[idx];
    }
}

// ---------------- launch ----------------
extern "C" void kernel_launch(void* const* d_in, const int* in_sizes, int n_in,
                              void* d_out, int out_size)
{
    const float* x      = (const float*)d_in[0];
    const float* W_ih   = (const float*)d_in[1];
    const float* W_hh   = (const float*)d_in[2];
    const float* b_ih   = (const float*)d_in[3];
    const float* b_hh   = (const float*)d_in[4];
    const float* W_head = (const float*)d_in[5];
    const float* b_head = (const float*)d_in[6];
    const float* W_out  = (const float*)d_in[7];
    const float* b_out  = (const float*)d_in[8];

    float* out   = (float*)d_out;                 // (B, T, O)
    float* mem   = out + BDIM * TDIM * ODIM;      // (B, MS, HS)
    float* out_h = mem + (size_t)BDIM * MS * HS;  // (B, H)
    float* out_c = out_h + BDIM * HDIM;           // (B, H)

    k_persist<<<NB, 256>>>(x, W_ih, W_hh, b_ih, b_hh, W_head, b_head,
                           W_out, b_out, out, mem, out_h, out_c);
}

// round 7
// speedup vs baseline: 1.5176x; 1.5176x over previous
#include <cuda_runtime.h>
#include <math.h>

#define BDIM 32
#define TDIM 32
#define IDIM 256
#define HDIM 512
#define HS 64
#define MS 2048
#define NHEADS 4
#define ODIM 256
#define NKEYS 8          // 4 read + 4 write
#define LCHUNKS 16       // logits chunks per batch (128 rows each)

// ---------------- persistent state (no allocations allowed) ----------------
__device__ float g_h[2][BDIM * HDIM];
__device__ float g_c[BDIM * HDIM];
__device__ float g_read[BDIM * NHEADS * HS];
__device__ float g_rk[BDIM * NHEADS * HS];
__device__ float g_wk[BDIM * NHEADS * HS];
__device__ float g_ws[BDIM * NHEADS];
__device__ float g_logits[BDIM * NKEYS * MS];
__device__ float g_pmax[BDIM * NKEYS * LCHUNKS];
__device__ float g_psum[BDIM * NKEYS * LCHUNKS];
__device__ float g_rpart[BDIM * 32 * NHEADS * HS];
__device__ unsigned g_cnt[BDIM];   // zero-init; reset by last block each step

__device__ __forceinline__ float sigmoidf_(float x) { return 1.f / (1.f + expf(-x)); }

// ---------------- init ----------------
__global__ void k_init(float* __restrict__ mem) {
    int idx = blockIdx.x * 256 + threadIdx.x;
    if (idx < BDIM * HDIM) { g_h[0][idx] = 0.f; g_c[idx] = 0.f; }
    if (idx < BDIM * NHEADS * HS) g_read[idx] = 0.f;
    if (idx < BDIM * MS * HS) mem[idx] = 0.f;
}

// ---------------- out(t-1) body (used inside fused lstm kernel + final) ----------------
__device__ __forceinline__ void out_body(
    const float* __restrict__ W_out, const float* __restrict__ b_out,
    float* __restrict__ out, const float* __restrict__ h_prev, int t, int og, int bg)
{
    __shared__ float cat_s[8][768];
    int tid = threadIdx.x;
    int bb0 = bg * 8;
    for (int idx = tid; idx < 8 * 768; idx += 256) {
        int bb = idx / 768, k = idx % 768;
        cat_s[bb][k] = (k < 512) ? h_prev[(bb0 + bb) * HDIM + k]
                                 : g_read[(bb0 + bb) * 256 + (k - 512)];
    }
    __syncthreads();
    int w = tid >> 5, lane = tid & 31;
    int o = og * 8 + w;
    float acc[8];
#pragma unroll
    for (int bb = 0; bb < 8; bb++) acc[bb] = 0.f;
#pragma unroll
    for (int c = 0; c < 6; c++) {
        int kw = c * 128 + lane * 4;
        float4 w4 = *(const float4*)&W_out[(size_t)o * 768 + kw];
#pragma unroll
        for (int bb = 0; bb < 8; bb++) {
            float4 a4 = *(const float4*)&cat_s[bb][kw];
            acc[bb] = fmaf(w4.x, a4.x, acc[bb]);
            acc[bb] = fmaf(w4.y, a4.y, acc[bb]);
            acc[bb] = fmaf(w4.z, a4.z, acc[bb]);
            acc[bb] = fmaf(w4.w, a4.w, acc[bb]);
        }
    }
    float res = 0.f;
#pragma unroll
    for (int bb = 0; bb < 8; bb++) {
        float v = acc[bb];
        v += __shfl_xor_sync(0xffffffffu, v, 16);
        v += __shfl_xor_sync(0xffffffffu, v, 8);
        v += __shfl_xor_sync(0xffffffffu, v, 4);
        v += __shfl_xor_sync(0xffffffffu, v, 2);
        v += __shfl_xor_sync(0xffffffffu, v, 1);
        if (lane == bb) res = v;
    }
    if (lane < 8) {
        int b = bb0 + lane;
        out[((size_t)b * TDIM + t) * ODIM + o] = res + b_out[o];
    }
}

// ---------------- K1: gate GEMM + LSTM cell, with out(t-1) fused as extra blocks ----------------
__global__ void __launch_bounds__(256) k_lstm(
    const float* __restrict__ x, const float* __restrict__ W_ih,
    const float* __restrict__ W_hh, const float* __restrict__ b_ih,
    const float* __restrict__ b_hh, const float* __restrict__ W_out,
    const float* __restrict__ b_out, float* __restrict__ out, int p, int t)
{
    if (blockIdx.x >= 64) {   // out(t-1) blocks (only launched when t>0)
        out_body(W_out, b_out, out, g_h[p], t - 1, blockIdx.x - 64, blockIdx.y);
        return;
    }
    __shared__ float inp_s[8][1024];
    const float* __restrict__ h_prev = g_h[p];
    float* __restrict__ h_new = g_h[p ^ 1];
    int tid = threadIdx.x;
    int bb0 = blockIdx.y * 8;
    for (int idx = tid; idx < 8 * 1024; idx += 256) {
        int bb = idx >> 10, k = idx & 1023;
        int b = bb0 + bb;
        float v;
        if (k < 256)      v = x[(b * TDIM + t) * IDIM + k];
        else if (k < 512) v = g_read[b * 256 + (k - 256)];
        else              v = h_prev[b * HDIM + (k - 512)];
        inp_s[bb][k] = v;
    }
    __syncthreads();
    int w = tid >> 5, lane = tid & 31;
    int j = blockIdx.x * 8 + w;
    float acc[4][8];
#pragma unroll
    for (int g = 0; g < 4; g++)
#pragma unroll
        for (int bb = 0; bb < 8; bb++) acc[g][bb] = 0.f;

#pragma unroll
    for (int c = 0; c < 8; c++) {
        const float* Wsrc = (c < 4) ? W_ih : W_hh;
        int kw = ((c & 3) * 128) + lane * 4;
        float4 w4[4];
#pragma unroll
        for (int g = 0; g < 4; g++)
            w4[g] = *(const float4*)&Wsrc[(size_t)(g * HDIM + j) * HDIM + kw];
        int ks = c * 128 + lane * 4;
#pragma unroll
        for (int bb = 0; bb < 8; bb++) {
            float4 a4 = *(const float4*)&inp_s[bb][ks];
#pragma unroll
            for (int g = 0; g < 4; g++) {
                acc[g][bb] = fmaf(w4[g].x, a4.x, acc[g][bb]);
                acc[g][bb] = fmaf(w4[g].y, a4.y, acc[g][bb]);
                acc[g][bb] = fmaf(w4[g].z, a4.z, acc[g][bb]);
                acc[g][bb] = fmaf(w4[g].w, a4.w, acc[g][bb]);
            }
        }
    }
    float res = 0.f;
#pragma unroll
    for (int g = 0; g < 4; g++)
#pragma unroll
        for (int bb = 0; bb < 8; bb++) {
            float v = acc[g][bb];
            v += __shfl_xor_sync(0xffffffffu, v, 16);
            v += __shfl_xor_sync(0xffffffffu, v, 8);
            v += __shfl_xor_sync(0xffffffffu, v, 4);
            v += __shfl_xor_sync(0xffffffffu, v, 2);
            v += __shfl_xor_sync(0xffffffffu, v, 1);
            if (lane == g * 8 + bb) res = v;
        }
    int bb = lane & 7;
    float iv = __shfl_sync(0xffffffffu, res, bb);
    float fv = __shfl_sync(0xffffffffu, res, 8 + bb);
    float gv = __shfl_sync(0xffffffffu, res, 16 + bb);
    float ov = __shfl_sync(0xffffffffu, res, 24 + bb);
    if (lane < 8) {
        int b = bb0 + lane;
        iv += b_ih[j] + b_hh[j];
        fv += b_ih[HDIM + j] + b_hh[HDIM + j];
        gv += b_ih[2 * HDIM + j] + b_hh[2 * HDIM + j];
        ov += b_ih[3 * HDIM + j] + b_hh[3 * HDIM + j];
        float cold = g_c[b * HDIM + j];
        float cn = sigmoidf_(fv) * cold + sigmoidf_(iv) * tanhf(gv);
        float hn = sigmoidf_(ov) * tanhf(cn);
        g_c[b * HDIM + j] = cn;
        h_new[b * HDIM + j] = hn;
    }
}

// ---------------- K2: head projection (129 used columns per head) ----------------
__global__ void __launch_bounds__(256) k_head(
    const float* __restrict__ W_head, const float* __restrict__ b_head, int pn)
{
    __shared__ float h_s[8][512];
    const float* __restrict__ h_new = g_h[pn];
    int tid = threadIdx.x;
    int bb0 = blockIdx.y * 8;
    for (int idx = tid; idx < 8 * 512; idx += 256) {
        int bb = idx >> 9, k = idx & 511;
        h_s[bb][k] = h_new[(bb0 + bb) * HDIM + k];
    }
    __syncthreads();
    int w = tid >> 5, lane = tid & 31;
    int r = blockIdx.x * 8 + w;
    if (r >= NHEADS * 129) return;
    int n = r / 129, jj = r % 129;
    int wrow = n * 2115 + jj;
    float acc[8];
#pragma unroll
    for (int bb = 0; bb < 8; bb++) acc[bb] = 0.f;
#pragma unroll
    for (int c = 0; c < 4; c++) {
        int kw = c * 128 + lane * 4;
        float4 w4 = *(const float4*)&W_head[(size_t)wrow * HDIM + kw];
#pragma unroll
        for (int bb = 0; bb < 8; bb++) {
            float4 a4 = *(const float4*)&h_s[bb][kw];
            acc[bb] = fmaf(w4.x, a4.x, acc[bb]);
            acc[bb] = fmaf(w4.y, a4.y, acc[bb]);
            acc[bb] = fmaf(w4.z, a4.z, acc[bb]);
            acc[bb] = fmaf(w4.w, a4.w, acc[bb]);
        }
    }
    float res = 0.f;
#pragma unroll
    for (int bb = 0; bb < 8; bb++) {
        float v = acc[bb];
        v += __shfl_xor_sync(0xffffffffu, v, 16);
        v += __shfl_xor_sync(0xffffffffu, v, 8);
        v += __shfl_xor_sync(0xffffffffu, v, 4);
        v += __shfl_xor_sync(0xffffffffu, v, 2);
        v += __shfl_xor_sync(0xffffffffu, v, 1);
        if (lane == bb) res = v;
    }
    if (lane < 8) {
        int b = bb0 + lane;
        float val = res + b_head[wrow];
        if (jj < HS)          g_rk[(b * NHEADS + n) * HS + jj] = val;
        else if (jj < 2 * HS) g_wk[(b * NHEADS + n) * HS + (jj - HS)] = val;
        else                  g_ws[b * NHEADS + n] = sigmoidf_(val);
    }
}

// ---------------- K3: logits (R1 shape: thread = 1 row x 4 keys) + softmax partials ----------------
// grid (16, 32): chunk of 128 rows, batch. tid>>7 selects read/write key group.
__global__ void __launch_bounds__(256) k_logits(const float* __restrict__ mem)
{
    __shared__ float key_s[NKEYS][64];
    __shared__ float wred[NKEYS][4];   // 4 warps per key group
    __shared__ float bmax[NKEYS];
    int tid = threadIdx.x;
    int b = blockIdx.y, chunk = blockIdx.x;
    for (int idx = tid; idx < NKEYS * 64; idx += 256) {
        int key = idx >> 6, h = idx & 63, n = key & 3;
        key_s[key][h] = (key < 4) ? g_rk[(b * NHEADS + n) * HS + h]
                                  : g_wk[(b * NHEADS + n) * HS + h];
    }
    __syncthreads();
    int kg = tid >> 7;                  // 0: read keys, 1: write keys
    int m = chunk * 128 + (tid & 127);
    float acc[4] = {0.f, 0.f, 0.f, 0.f};
    const float* mrow = &mem[((size_t)b * MS + m) * HS];
#pragma unroll
    for (int hq = 0; hq < 16; hq++) {
        float4 v = *(const float4*)&mrow[hq * 4];
#pragma unroll
        for (int kk = 0; kk < 4; kk++) {
            float4 kv = *(const float4*)&key_s[kg * 4 + kk][hq * 4];
            acc[kk] = fmaf(v.x, kv.x, acc[kk]);
            acc[kk] = fmaf(v.y, kv.y, acc[kk]);
            acc[kk] = fmaf(v.z, kv.z, acc[kk]);
            acc[kk] = fmaf(v.w, kv.w, acc[kk]);
        }
    }
    const float scale = 0.125f;
#pragma unroll
    for (int kk = 0; kk < 4; kk++) {
        acc[kk] *= scale;
        g_logits[((size_t)b * NKEYS + kg * 4 + kk) * MS + m] = acc[kk];
    }
    // per-block softmax partials (max + sum-exp) per key
    int w4 = (tid >> 5) & 3, lane = tid & 31;
#pragma unroll
    for (int kk = 0; kk < 4; kk++) {
        float v = acc[kk];
        v = fmaxf(v, __shfl_xor_sync(0xffffffffu, v, 16));
        v = fmaxf(v, __shfl_xor_sync(0xffffffffu, v, 8));
        v = fmaxf(v, __shfl_xor_sync(0xffffffffu, v, 4));
        v = fmaxf(v, __shfl_xor_sync(0xffffffffu, v, 2));
        v = fmaxf(v, __shfl_xor_sync(0xffffffffu, v, 1));
        if (lane == 0) wred[kg * 4 + kk][w4] = v;
    }
    __syncthreads();
    if (tid < NKEYS)
        bmax[tid] = fmaxf(fmaxf(wred[tid][0], wred[tid][1]),
                          fmaxf(wred[tid][2], wred[tid][3]));
    __syncthreads();
#pragma unroll
    for (int kk = 0; kk < 4; kk++) {
        float v = expf(acc[kk] - bmax[kg * 4 + kk]);
        v += __shfl_xor_sync(0xffffffffu, v, 16);
        v += __shfl_xor_sync(0xffffffffu, v, 8);
        v += __shfl_xor_sync(0xffffffffu, v, 4);
        v += __shfl_xor_sync(0xffffffffu, v, 2);
        v += __shfl_xor_sync(0xffffffffu, v, 1);
        if (lane == 0) wred[kg * 4 + kk][w4] = v;
    }
    __syncthreads();
    if (tid < NKEYS) {
        float s = wred[tid][0] + wred[tid][1] + wred[tid][2] + wred[tid][3];
        g_pmax[(b * NKEYS + tid) * LCHUNKS + chunk] = bmax[tid];
        g_psum[(b * NKEYS + tid) * LCHUNKS + chunk] = s;
    }
}

// ---------------- K4: softmax finalize + single-pass read/update + last-block read reduce ----------------
// grid (32, 32): chunk of 64 rows, batch.
__global__ void __launch_bounds__(256) k_attend(float* __restrict__ mem)
{
    __shared__ float gm[NKEYS], ginv[NKEYS];
    __shared__ float w_s[NKEYS][64];
    __shared__ float swk_s[NHEADS][64];
    __shared__ float sred[4][NHEADS * 64];
    __shared__ unsigned is_last;
    int tid = threadIdx.x;
    int chunk = blockIdx.x, b = blockIdx.y;

    if (tid < NKEYS) {
        const float* pm = &g_pmax[(b * NKEYS + tid) * LCHUNKS];
        const float* ps = &g_psum[(b * NKEYS + tid) * LCHUNKS];
        float m0 = pm[0];
#pragma unroll
        for (int i = 1; i < LCHUNKS; i++) m0 = fmaxf(m0, pm[i]);
        float s = 0.f;
#pragma unroll
        for (int i = 0; i < LCHUNKS; i++) s += expf(pm[i] - m0) * ps[i];
        gm[tid] = m0;
        ginv[tid] = 1.f / s;
    }
    {
        int n = tid >> 6, h = tid & 63;
        swk_s[n][h] = g_ws[b * NHEADS + n] * g_wk[(b * NHEADS + n) * HS + h];
    }
    __syncthreads();
    for (int idx = tid; idx < NKEYS * 64; idx += 256) {
        int key = idx >> 6, row = idx & 63;
        float lg = g_logits[((size_t)b * NKEYS + key) * MS + chunk * 64 + row];
        w_s[key][row] = expf(lg - gm[key]) * ginv[key];
    }
    __syncthreads();

    int h = tid & 63, ms = tid >> 6;
    float v[16];
    float acc[NHEADS] = {0.f, 0.f, 0.f, 0.f};
#pragma unroll
    for (int mi = 0; mi < 16; mi++) {
        int row = mi * 4 + ms;
        v[mi] = mem[((size_t)b * MS + chunk * 64 + row) * HS + h];
#pragma unroll
        for (int n = 0; n < NHEADS; n++)
            acc[n] = fmaf(w_s[n][row], v[mi], acc[n]);
    }
#pragma unroll
    for (int mi = 0; mi < 16; mi++) {
        int row = mi * 4 + ms;
        float val = v[mi];
#pragma unroll
        for (int n = 0; n < NHEADS; n++)
            val = fmaf(w_s[4 + n][row], swk_s[n][h], val);
        mem[((size_t)b * MS + chunk * 64 + row) * HS + h] = val;
    }
#pragma unroll
    for (int n = 0; n < NHEADS; n++) sred[ms][n * 64 + h] = acc[n];
    __syncthreads();
    float tot = sred[0][tid] + sred[1][tid] + sred[2][tid] + sred[3][tid];
    g_rpart[((size_t)b * 32 + chunk) * 256 + tid] = tot;

    // deterministic last-block reduction into g_read
    __threadfence();
    if (tid == 0) is_last = (atomicAdd(&g_cnt[b], 1u) == 31u) ? 1u : 0u;
    __syncthreads();
    if (is_last) {
        if (tid == 0) g_cnt[b] = 0u;   // reset for next step / next replay
        __threadfence();
        float s = 0.f;
#pragma unroll
        for (int ch = 0; ch < 32; ch++)
            s += g_rpart[((size_t)b * 32 + ch) * 256 + tid];
        g_read[b * 256 + tid] = s;
    }
}

// ---------------- final: out(31) + state copy ----------------
__global__ void __launch_bounds__(256) k_last(
    const float* __restrict__ W_out, const float* __restrict__ b_out,
    float* __restrict__ out, float* __restrict__ dst_h, float* __restrict__ dst_c)
{
    if (blockIdx.x < 32) {
        out_body(W_out, b_out, out, g_h[0], TDIM - 1, blockIdx.x, blockIdx.y);
    } else if (blockIdx.y == 0) {
        int idx = (blockIdx.x - 32) * 256 + threadIdx.x;
        if (idx < BDIM * HDIM) {
            dst_h[idx] = g_h[0][idx];   // after 32 steps h lives in buffer 0
            dst_c[idx] = g_c[idx];
        }
    }
}

// ---------------- launch ----------------
extern "C" void kernel_launch(void* const* d_in, const int* in_sizes, int n_in,
                              void* d_out, int out_size)
{
    const float* x      = (const float*)d_in[0];
    const float* W_ih   = (const float*)d_in[1];
    const float* W_hh   = (const float*)d_in[2];
    const float* b_ih   = (const float*)d_in[3];
    const float* b_hh   = (const float*)d_in[4];
    const float* W_head = (const float*)d_in[5];
    const float* b_head = (const float*)d_in[6];
    const float* W_out  = (const float*)d_in[7];
    const float* b_out  = (const float*)d_in[8];

    float* out   = (float*)d_out;                 // (B, T, O)
    float* mem   = out + BDIM * TDIM * ODIM;      // (B, MS, HS)
    float* out_h = mem + (size_t)BDIM * MS * HS;  // (B, H)
    float* out_c = out_h + BDIM * HDIM;           // (B, H)

    k_init<<<(BDIM * MS * HS) / 256, 256>>>(mem);

    for (int t = 0; t < TDIM; t++) {
        int p = t & 1;
        int pn = p ^ 1;
        int gx = (t > 0) ? 96 : 64;   // fuse out(t-1) blocks when t>0
        k_lstm<<<dim3(gx, 4), 256>>>(x, W_ih, W_hh, b_ih, b_hh,
                                     W_out, b_out, out, p, t);
        k_head<<<dim3(65, 4), 256>>>(W_head, b_head, pn);
        k_logits<<<dim3(LCHUNKS, 32), 256>>>(mem);
        k_attend<<<dim3(32, 32), 256>>>(mem);
    }
    k_last<<<dim3(96, 4), 256>>>(W_out, b_out, out, out_h, out_c);
}